// round 1
// baseline (speedup 1.0000x reference)
#include <cuda_runtime.h>
#include <cuda_bf16.h>
#include <mma.h>

using namespace nvcuda;

// Problem constants
#define BATCH 4
#define SEQ 8192
#define DM 1024
#define NH 16
#define HD 64
#define NCHUNK 32          // SEQ / 256
#define MTOT (BATCH * SEQ) // 32768

// -------------------- scratch (static device globals; no allocs) -----------
__device__ float g_q[MTOT * DM];
__device__ float g_k[MTOT * DM];
__device__ float g_v[MTOT * DM];
__device__ float g_att[MTOT * DM];

// ===========================================================================
// GEMM: C[M,N] = A[M,K] @ B[K,N], fp32 in/out, bf16x3 split (hi/lo) with
// fp32 accumulation via WMMA 16x16x16. Error ~2^-16 relative.
// Block tile 128x128, BK=16, 8 warps (2x4), warp tile 64x32 (4x2 frags).
// ===========================================================================
#define GBM 128
#define GBN 128
#define GBK 16

__device__ __forceinline__ void cvt_store4(__nv_bfloat16* h, __nv_bfloat16* l, float4 v) {
    float f[4] = {v.x, v.y, v.z, v.w};
#pragma unroll
    for (int i = 0; i < 4; i++) {
        __nv_bfloat16 hi = __float2bfloat16_rn(f[i]);
        float r = f[i] - __bfloat162float(hi);
        h[i] = hi;
        l[i] = __float2bfloat16_rn(r);
    }
}

__global__ __launch_bounds__(256, 2) void gemm_bf16x3(
    const float* __restrict__ A, const float* __restrict__ Bm,
    float* __restrict__ C, int M, int N, int K)
{
    __shared__ __nv_bfloat16 Ah[GBM * GBK], Al[GBM * GBK];
    __shared__ __nv_bfloat16 Bh[GBK * GBN], Bl[GBK * GBN];

    const int tid = threadIdx.x;
    const int warp = tid >> 5;
    const int wm = warp >> 2; // 0..1
    const int wn = warp & 3;  // 0..3
    const int bm = blockIdx.y * GBM;
    const int bn = blockIdx.x * GBN;

    wmma::fragment<wmma::accumulator, 16, 16, 16, float> acc[4][2];
#pragma unroll
    for (int i = 0; i < 4; i++)
#pragma unroll
        for (int j = 0; j < 2; j++)
            wmma::fill_fragment(acc[i][j], 0.0f);

    for (int k0 = 0; k0 < K; k0 += GBK) {
        // Load A tile (128x16) and B tile (16x128): 512 float4 each, 2 per thread
#pragma unroll
        for (int t = 0; t < 2; t++) {
            int idx = tid * 2 + t;
            {
                int row = idx >> 2;
                int c = (idx & 3) << 2;
                float4 va = *reinterpret_cast<const float4*>(
                    A + (size_t)(bm + row) * K + k0 + c);
                int off = row * GBK + c;
                cvt_store4(Ah + off, Al + off, va);
            }
            {
                int rb = idx >> 5;
                int cb = (idx & 31) << 2;
                float4 vb = *reinterpret_cast<const float4*>(
                    Bm + (size_t)(k0 + rb) * N + bn + cb);
                int off = rb * GBN + cb;
                cvt_store4(Bh + off, Bl + off, vb);
            }
        }
        __syncthreads();

        wmma::fragment<wmma::matrix_a, 16, 16, 16, __nv_bfloat16, wmma::row_major> ah[4], al[4];
        wmma::fragment<wmma::matrix_b, 16, 16, 16, __nv_bfloat16, wmma::row_major> bh[2], bl[2];
#pragma unroll
        for (int i = 0; i < 4; i++) {
            wmma::load_matrix_sync(ah[i], Ah + (wm * 64 + i * 16) * GBK, GBK);
            wmma::load_matrix_sync(al[i], Al + (wm * 64 + i * 16) * GBK, GBK);
        }
#pragma unroll
        for (int j = 0; j < 2; j++) {
            wmma::load_matrix_sync(bh[j], Bh + wn * 32 + j * 16, GBN);
            wmma::load_matrix_sync(bl[j], Bl + wn * 32 + j * 16, GBN);
        }
#pragma unroll
        for (int i = 0; i < 4; i++)
#pragma unroll
            for (int j = 0; j < 2; j++) {
                wmma::mma_sync(acc[i][j], al[i], bh[j], acc[i][j]);
                wmma::mma_sync(acc[i][j], ah[i], bl[j], acc[i][j]);
                wmma::mma_sync(acc[i][j], ah[i], bh[j], acc[i][j]);
            }
        __syncthreads();
    }

#pragma unroll
    for (int i = 0; i < 4; i++)
#pragma unroll
        for (int j = 0; j < 2; j++)
            wmma::store_matrix_sync(
                C + (size_t)(bm + wm * 64 + i * 16) * N + bn + wn * 32 + j * 16,
                acc[i][j], N, wmma::mem_row_major);
}

// ===========================================================================
// Chunked local attention. Window = 64 (inclusive: j in [i-64, i]).
// One block per (batch, chunk, head, 64-row tile). Column coverage for row
// tile r: chunk cols [64r-64, 64r+64) -> 128 columns.
// Dynamic smem: Qs 64x65, Ks 128x65, Vs 128x65, Ss 64x130 (fp32).
// ===========================================================================
#define ATTN_SMEM_FLOATS (64 * 65 + 128 * 65 + 128 * 65 + 64 * 130)
#define ATTN_SMEM_BYTES (ATTN_SMEM_FLOATS * 4)

__global__ __launch_bounds__(128) void attn_kernel(
    const float* __restrict__ q, const float* __restrict__ k,
    const float* __restrict__ v, float* __restrict__ o)
{
    extern __shared__ float smem[];
    float* Qs = smem;             // [64][65]
    float* Ks = Qs + 64 * 65;     // [128][65]
    float* Vs = Ks + 128 * 65;    // [128][65]
    float* Ss = Vs + 128 * 65;    // [64][130]

    const int bid = blockIdx.x;
    const int rtile = bid & 3;
    const int head = (bid >> 2) & 15;
    const int chunk = (bid >> 6) & (NCHUNK - 1);
    const int b = bid >> 11;

    const int tid = threadIdx.x;
    const int c0 = rtile * 64 - 64; // chunk-col of Ks row 0 (may be negative)
    const size_t base = ((size_t)(b * SEQ + chunk * 256)) * DM + head * HD;

    // ---- stage Q (64x64) ----
    for (int idx = tid; idx < 64 * 16; idx += 128) {
        int row = idx >> 4;
        int c = (idx & 15) << 2;
        float4 val = *reinterpret_cast<const float4*>(
            q + base + (size_t)(rtile * 64 + row) * DM + c);
        float* dst = Qs + row * 65 + c;
        dst[0] = val.x; dst[1] = val.y; dst[2] = val.z; dst[3] = val.w;
    }
    // ---- stage K, V (128x64), zero-fill out-of-chunk rows ----
    for (int idx = tid; idx < 128 * 16; idx += 128) {
        int row = idx >> 4;
        int c = (idx & 15) << 2;
        int jc = c0 + row;
        float4 kv = make_float4(0.f, 0.f, 0.f, 0.f);
        float4 vv = make_float4(0.f, 0.f, 0.f, 0.f);
        if (jc >= 0) {
            kv = *reinterpret_cast<const float4*>(k + base + (size_t)jc * DM + c);
            vv = *reinterpret_cast<const float4*>(v + base + (size_t)jc * DM + c);
        }
        float* dk = Ks + row * 65 + c;
        dk[0] = kv.x; dk[1] = kv.y; dk[2] = kv.z; dk[3] = kv.w;
        float* dv = Vs + row * 65 + c;
        dv[0] = vv.x; dv[1] = vv.y; dv[2] = vv.z; dv[3] = vv.w;
    }
    __syncthreads();

    // ---- scores: S[64][128] = Q @ K^T * scale ----
    {
        const int rg = tid >> 3; // 0..15 (rows rg, rg+16, rg+32, rg+48)
        const int cg = tid & 7;  // 0..7  (cols cg + 8*jj)
        float acc[4][16];
#pragma unroll
        for (int r = 0; r < 4; r++)
#pragma unroll
            for (int jj = 0; jj < 16; jj++) acc[r][jj] = 0.f;

        for (int d = 0; d < 64; d++) {
            float qv0 = Qs[rg * 65 + d];
            float qv1 = Qs[(rg + 16) * 65 + d];
            float qv2 = Qs[(rg + 32) * 65 + d];
            float qv3 = Qs[(rg + 48) * 65 + d];
#pragma unroll
            for (int jj = 0; jj < 16; jj++) {
                float kv = Ks[(cg + 8 * jj) * 65 + d];
                acc[0][jj] += qv0 * kv;
                acc[1][jj] += qv1 * kv;
                acc[2][jj] += qv2 * kv;
                acc[3][jj] += qv3 * kv;
            }
        }
        const float scale = 0.125f; // 1/sqrt(64)
#pragma unroll
        for (int r = 0; r < 4; r++)
#pragma unroll
            for (int jj = 0; jj < 16; jj++)
                Ss[(rg + 16 * r) * 130 + cg + 8 * jj] = acc[r][jj] * scale;
    }
    __syncthreads();

    // ---- masked softmax per row: valid jj in [lo, i+64] ----
    {
        const int i = tid >> 1;
        const int half = tid & 1;
        const int lo = (rtile == 0) ? 64 : i; // for rtile 0, rows clamp at chunk start
        const int hi = i + 64;
        float* row = Ss + i * 130 + half * 64;
        const int jbase = half * 64;

        float m = -1e30f;
#pragma unroll
        for (int jj = 0; jj < 64; jj++) {
            int j = jbase + jj;
            if (j >= lo && j <= hi) m = fmaxf(m, row[jj]);
        }
        m = fmaxf(m, __shfl_xor_sync(0xffffffffu, m, 1));

        float s = 0.f;
#pragma unroll
        for (int jj = 0; jj < 64; jj++) {
            int j = jbase + jj;
            float e = 0.f;
            if (j >= lo && j <= hi) {
                e = __expf(row[jj] - m);
                s += e;
            }
            row[jj] = e;
        }
        s += __shfl_xor_sync(0xffffffffu, s, 1);
        float inv = 1.0f / s;
#pragma unroll
        for (int jj = 0; jj < 64; jj++) row[jj] *= inv;
    }
    __syncthreads();

    // ---- out = P @ V : [64][64] ----
    {
        const int rg = tid >> 2; // 0..31 (rows rg, rg+32)
        const int cg = tid & 3;  // 0..3 (d base = cg*16)
        float acc0[16], acc1[16];
#pragma unroll
        for (int dd = 0; dd < 16; dd++) { acc0[dd] = 0.f; acc1[dd] = 0.f; }

        for (int j = 0; j < 128; j++) {
            float p0 = Ss[rg * 130 + j];
            float p1 = Ss[(rg + 32) * 130 + j];
#pragma unroll
            for (int dd = 0; dd < 16; dd++) {
                float vv = Vs[j * 65 + cg * 16 + dd];
                acc0[dd] += p0 * vv;
                acc1[dd] += p1 * vv;
            }
        }
#pragma unroll
        for (int r = 0; r < 2; r++) {
            const float* accp = r ? acc1 : acc0;
            size_t off = base + (size_t)(rtile * 64 + rg + 32 * r) * DM + cg * 16;
#pragma unroll
            for (int d4 = 0; d4 < 4; d4++) {
                float4 val = make_float4(accp[d4 * 4 + 0], accp[d4 * 4 + 1],
                                         accp[d4 * 4 + 2], accp[d4 * 4 + 3]);
                *reinterpret_cast<float4*>(o + off + d4 * 4) = val;
            }
        }
    }
}

// ===========================================================================
// kernel_launch
// ===========================================================================
extern "C" void kernel_launch(void* const* d_in, const int* in_sizes, int n_in,
                              void* d_out, int out_size)
{
    (void)in_sizes; (void)n_in; (void)out_size;
    const float* x  = (const float*)d_in[0];
    const float* Wq = (const float*)d_in[1];
    const float* Wk = (const float*)d_in[2];
    const float* Wv = (const float*)d_in[3];
    const float* Wo = (const float*)d_in[4];
    float* out = (float*)d_out;

    float *q, *k, *v, *att;
    cudaGetSymbolAddress((void**)&q, g_q);
    cudaGetSymbolAddress((void**)&k, g_k);
    cudaGetSymbolAddress((void**)&v, g_v);
    cudaGetSymbolAddress((void**)&att, g_att);

    cudaFuncSetAttribute(attn_kernel, cudaFuncAttributeMaxDynamicSharedMemorySize,
                         ATTN_SMEM_BYTES);

    dim3 ggrid(DM / GBN, MTOT / GBM); // (8, 256)
    gemm_bf16x3<<<ggrid, 256>>>(x, Wq, q, MTOT, DM, DM);
    gemm_bf16x3<<<ggrid, 256>>>(x, Wk, k, MTOT, DM, DM);
    gemm_bf16x3<<<ggrid, 256>>>(x, Wv, v, MTOT, DM, DM);

    attn_kernel<<<BATCH * NCHUNK * NH * 4, 128, ATTN_SMEM_BYTES>>>(q, k, v, att);

    gemm_bf16x3<<<ggrid, 256>>>(att, Wo, out, MTOT, DM, DM);
}

// round 3
// speedup vs baseline: 2.4678x; 2.4678x over previous
#include <cuda_runtime.h>
#include <cuda_bf16.h>
#include <mma.h>
#include <cstdint>

using namespace nvcuda;

// ---------------- problem constants ----------------
#define BATCH 4
#define SEQ 8192
#define DM 1024
#define NH 16
#define HD 64
#define NCHUNK 32
#define MTOT (BATCH * SEQ) // 32768

// Feature gate: tcgen05 only exists in the compute_103a / compute_100a passes.
#if defined(__CUDA_ARCH__) && (defined(__CUDA_ARCH_FEAT_SM103_ALL) || defined(__CUDA_ARCH_FEAT_SM100_ALL))
#define HAS_TCGEN05 1
#else
#define HAS_TCGEN05 0
#endif

// ---------------- scratch (device globals; no allocs) ----------------
__device__ float g_q[MTOT * DM];
__device__ float g_k[MTOT * DM];
__device__ float g_v[MTOT * DM];
__device__ __nv_bfloat16 g_ah[MTOT * DM]; // hi split of x, later of attn-out
__device__ __nv_bfloat16 g_al[MTOT * DM]; // lo split
__device__ __nv_bfloat16 g_wh[4 * DM * DM]; // transposed weights hi (q,k,v,o)
__device__ __nv_bfloat16 g_wl[4 * DM * DM]; // transposed weights lo

// ---------------- PTX helpers (legal on base sm_103) ----------------
__device__ __forceinline__ uint32_t elect_one_pred() {
    uint32_t pred;
    asm volatile(
        "{\n\t.reg .pred p;\n\t"
        "elect.sync _|p, 0xFFFFFFFF;\n\t"
        "selp.b32 %0, 1, 0, p;\n\t}"
        : "=r"(pred));
    return pred;
}

__device__ __forceinline__ uint32_t smem_to_u32(const void* smem_ptr) {
    uint32_t addr;
    asm("{ .reg .u64 tmp; cvta.to.shared.u64 tmp, %1; cvt.u32.u64 %0, tmp; }"
        : "=r"(addr) : "l"(smem_ptr));
    return addr;
}

#define MBARRIER_INIT(mbar, count) \
    asm volatile("mbarrier.init.shared.b64 [%0], %1;" \
                 :: "r"((uint32_t)(mbar)), "r"((uint32_t)(count)) : "memory")

#define MBARRIER_WAIT_PARITY(mbar_smem_addr, phase_parity) do { \
    uint32_t _mbar = (uint32_t)(mbar_smem_addr); \
    uint32_t _parity = (uint32_t)(phase_parity); \
    uint32_t _done; \
    asm volatile( \
        "{\n\t.reg .pred p;\n\t" \
        "mbarrier.try_wait.parity.acquire.cta.shared::cta.b64 p, [%1], %2;\n\t" \
        "selp.b32 %0, 1, 0, p;\n\t}" \
        : "=r"(_done) : "r"(_mbar), "r"(_parity) : "memory"); \
    if (!_done) { \
        asm volatile( \
            "{\n\t.reg .pred P1;\n\t" \
            "WAIT_LOOP_%=:\n\t" \
            "mbarrier.try_wait.parity.acquire.cta.shared::cta.b64 P1, [%0], %1, 0x989680;\n\t" \
            "@P1 bra.uni WAIT_DONE_%=;\n\t" \
            "bra.uni WAIT_LOOP_%=;\n\t" \
            "WAIT_DONE_%=:\n\t}" \
            :: "r"(_mbar), "r"(_parity) : "memory"); \
    } \
} while (0)

#define FENCE_PROXY_ASYNC_SHARED_CTA() \
    asm volatile("fence.proxy.async.shared::cta;" ::: "memory")

#if HAS_TCGEN05
// ---------------- tcgen05 helpers (compute_103a pass only) ----------------
#define TCGEN05_ALLOC(smem_result_addr, nCols) \
    asm volatile("tcgen05.alloc.cta_group::1.sync.aligned.shared::cta.b32 [%0], %1;" \
                 :: "r"((uint32_t)(smem_result_addr)), "r"((uint32_t)(nCols)) : "memory")

#define TCGEN05_DEALLOC(tmem_addr, nCols) \
    asm volatile("tcgen05.dealloc.cta_group::1.sync.aligned.b32 %0, %1;" \
                 :: "r"(tmem_addr), "r"((uint32_t)(nCols)))

#define TCGEN05_RELINQUISH() \
    asm volatile("tcgen05.relinquish_alloc_permit.cta_group::1.sync.aligned;")

#define TCGEN05_COMMIT(mbar) \
    asm volatile("tcgen05.commit.cta_group::1.mbarrier::arrive::one.shared::cluster.b64 [%0];" \
                 :: "r"((uint32_t)(mbar)) : "memory")

#define TCGEN05_FENCE_AFTER() \
    asm volatile("tcgen05.fence::after_thread_sync;" ::: "memory")

#define TCGEN05_WAIT_LD() \
    asm volatile("tcgen05.wait::ld.sync.aligned;" ::: "memory")

#define TCGEN05_LD_32X32B_X32(r, tmem_addr) \
    asm volatile( \
        "tcgen05.ld.sync.aligned.32x32b.x32.b32 " \
        "{%0, %1, %2, %3, %4, %5, %6, %7, " \
        " %8, %9, %10, %11, %12, %13, %14, %15, " \
        " %16, %17, %18, %19, %20, %21, %22, %23, " \
        " %24, %25, %26, %27, %28, %29, %30, %31}, [%32];" \
        : "=r"((r)[0]),  "=r"((r)[1]),  "=r"((r)[2]),  "=r"((r)[3]), \
          "=r"((r)[4]),  "=r"((r)[5]),  "=r"((r)[6]),  "=r"((r)[7]), \
          "=r"((r)[8]),  "=r"((r)[9]),  "=r"((r)[10]), "=r"((r)[11]), \
          "=r"((r)[12]), "=r"((r)[13]), "=r"((r)[14]), "=r"((r)[15]), \
          "=r"((r)[16]), "=r"((r)[17]), "=r"((r)[18]), "=r"((r)[19]), \
          "=r"((r)[20]), "=r"((r)[21]), "=r"((r)[22]), "=r"((r)[23]), \
          "=r"((r)[24]), "=r"((r)[25]), "=r"((r)[26]), "=r"((r)[27]), \
          "=r"((r)[28]), "=r"((r)[29]), "=r"((r)[30]), "=r"((r)[31]) \
        : "r"(tmem_addr))

// SW128 K-major descriptor: LBO=1, SBO=64, version=1
static constexpr uint64_t SMEM_DESC_BASE_SW128 =
    (uint64_t(2) << 61) | (uint64_t(1) << 46) | (uint64_t(64) << 32) | (uint64_t(1) << 16);
#define MAKE_SMEM_DESC(base_addr) \
    (SMEM_DESC_BASE_SW128 | ((uint64_t)((base_addr) >> 4) & 0x3FFF))

__device__ __forceinline__ void tcgen05_mma_f16_ss_cg1(
    uint32_t d_tmem, uint64_t a_desc, uint64_t b_desc, uint32_t idesc, uint32_t en)
{
    asm volatile(
        "{\n\t.reg .pred p;\n\t"
        "setp.ne.u32 p, %5, 0;\n\t"
        "tcgen05.mma.cta_group::1.kind::f16 [%0], %1, %2, %3, {%4, %4, %4, %4}, p;\n\t}"
        :: "r"(d_tmem), "l"(a_desc), "l"(b_desc), "r"(idesc), "r"(0u), "r"(en)
        : "memory");
}

// idesc: dtype F32, atype/btype BF16, N=128, M=128
#define GEMM_IDESC ((1u << 4) | (1u << 7) | (1u << 10) | (16u << 17) | (8u << 24))
#endif // HAS_TCGEN05

__device__ __forceinline__ void split1(float x, __nv_bfloat16& h, __nv_bfloat16& l) {
    h = __float2bfloat16_rn(x);
    l = __float2bfloat16_rn(x - __bfloat162float(h));
}

// ===========================================================================
// prep: split fp32 -> bf16 hi/lo
// ===========================================================================
__global__ __launch_bounds__(256) void splitx_kernel(
    const float4* __restrict__ in, __nv_bfloat162* __restrict__ h,
    __nv_bfloat162* __restrict__ l)
{
    size_t i = (size_t)blockIdx.x * 256 + threadIdx.x;
    float4 v = in[i];
    __nv_bfloat16 h0, h1, h2, h3, l0, l1, l2, l3;
    split1(v.x, h0, l0); split1(v.y, h1, l1);
    split1(v.z, h2, l2); split1(v.w, h3, l3);
    __nv_bfloat162 a; a.x = h0; a.y = h1;
    __nv_bfloat162 b; b.x = h2; b.y = h3;
    __nv_bfloat162 c; c.x = l0; c.y = l1;
    __nv_bfloat162 d; d.x = l2; d.y = l3;
    h[2 * i] = a; h[2 * i + 1] = b;
    l[2 * i] = c; l[2 * i + 1] = d;
}

// ===========================================================================
// prep: W[K,N] fp32 -> Wt[N,K] bf16 hi/lo (transpose + split)
// ===========================================================================
__global__ __launch_bounds__(256) void wtrans_kernel(
    const float* __restrict__ W, __nv_bfloat16* __restrict__ th,
    __nv_bfloat16* __restrict__ tl)
{
    __shared__ float tile[32][33];
    const int n0 = blockIdx.x * 32, k0 = blockIdx.y * 32;
    const int tx = threadIdx.x, ty = threadIdx.y;
    for (int r = ty; r < 32; r += 8)
        tile[r][tx] = W[(size_t)(k0 + r) * DM + n0 + tx];
    __syncthreads();
    for (int r = ty; r < 32; r += 8) {
        float v = tile[tx][r];
        __nv_bfloat16 h, l;
        split1(v, h, l);
        size_t o = (size_t)(n0 + r) * DM + k0 + tx;
        th[o] = h;
        tl[o] = l;
    }
}

// ===========================================================================
// GEMM: C[M,1024] = A[M,1024] @ Bt[1024,1024]^T, bf16x3 (hi/lo pre-split),
// fp32 accumulation. Tile 128x128, 256 threads.
//   - compute_103a pass: tcgen05 SS MMA, TMEM accumulator, 3-stage pipeline.
//   - base sm_103 pass:  WMMA (HMMA) fallback, BK=64 single buffer.
// ===========================================================================
#define KCH 64
#define NCHK (DM / KCH) // 16
#define NSTAGE 3
#define TILE_B (128 * 128)       // 16KB per bf16 tile (128 rows x 128B)
#define STAGE_B (4 * TILE_B)     // Ah, Al, Bh, Bl
#define GEMM_SMEM (1024 + NSTAGE * STAGE_B) // 197632 bytes

__global__ __launch_bounds__(256, 1) void gemm_tc(
    const __nv_bfloat16* __restrict__ Ahg, const __nv_bfloat16* __restrict__ Alg,
    const __nv_bfloat16* __restrict__ Bhg, const __nv_bfloat16* __restrict__ Blg,
    float* __restrict__ C)
{
    extern __shared__ char smem[];
    const int tid = threadIdx.x;
    const int wid = tid >> 5, lid = tid & 31;
    const int bm = blockIdx.y * 128, bn = blockIdx.x * 128;

    const __nv_bfloat16* pAh = Ahg + (size_t)bm * DM;
    const __nv_bfloat16* pAl = Alg + (size_t)bm * DM;
    const __nv_bfloat16* pBh = Bhg + (size_t)bn * DM;
    const __nv_bfloat16* pBl = Blg + (size_t)bn * DM;

    const int t16 = tid & 7;   // 16B unit within a 128B (64-elt) row
    const int r0 = tid >> 3;   // 0..31

#if HAS_TCGEN05
    const uint32_t smem_base = smem_to_u32(smem);
    if (tid == 0) {
#pragma unroll
        for (int s = 0; s < NSTAGE; s++) MBARRIER_INIT(smem_base + 16 + 8 * s, 1);
    }
    if (wid == 0) {
        TCGEN05_ALLOC(smem_base, 128);
    }
    __syncthreads();
    uint32_t tmem_base;
    asm volatile("ld.shared.b32 %0, [%1];" : "=r"(tmem_base) : "r"(smem_base));

#pragma unroll 1
    for (int c = 0; c < NCHK; c++) {
        const int b = c % NSTAGE;
        if (c >= NSTAGE) {
            const uint32_t par = ((uint32_t)(c / NSTAGE) - 1u) & 1u;
            MBARRIER_WAIT_PARITY(smem_base + 16 + 8 * b, par);
        }
        char* st = smem + 1024 + b * STAGE_B;
        const int kc = c * KCH;
#pragma unroll
        for (int p = 0; p < 16; p++) {
            const int mat = p >> 2;            // 0..3
            const int row = (p & 3) * 32 + r0; // 0..127
            const __nv_bfloat16* src =
                (mat == 0) ? pAh : (mat == 1) ? pAl : (mat == 2) ? pBh : pBl;
            uint4 val = *reinterpret_cast<const uint4*>(
                src + (size_t)row * DM + kc + t16 * 8);
            uint32_t off = (uint32_t)(row * 128 + t16 * 16);
            off ^= ((off >> 3) & 0x70);
            *reinterpret_cast<uint4*>(st + mat * TILE_B + off) = val;
        }
        FENCE_PROXY_ASYNC_SHARED_CTA();
        __syncthreads();
        if (wid == 0) {
            const uint32_t sb = smem_base + 1024 + b * STAGE_B;
            const uint64_t dAh = MAKE_SMEM_DESC(sb);
            const uint64_t dAl = MAKE_SMEM_DESC(sb + TILE_B);
            const uint64_t dBh = MAKE_SMEM_DESC(sb + 2 * TILE_B);
            const uint64_t dBl = MAKE_SMEM_DESC(sb + 3 * TILE_B);
            if (elect_one_pred()) {
#pragma unroll
                for (int j = 0; j < 4; j++) {
                    const uint32_t en0 = (c == 0 && j == 0) ? 0u : 1u;
                    tcgen05_mma_f16_ss_cg1(tmem_base, dAl + j * 2, dBh + j * 2, GEMM_IDESC, en0);
                    tcgen05_mma_f16_ss_cg1(tmem_base, dAh + j * 2, dBl + j * 2, GEMM_IDESC, 1u);
                    tcgen05_mma_f16_ss_cg1(tmem_base, dAh + j * 2, dBh + j * 2, GEMM_IDESC, 1u);
                }
                TCGEN05_COMMIT(smem_base + 16 + 8 * b);
            }
        }
    }

    {
        const int bl = (NCHK - 1) % NSTAGE;
        const uint32_t uses = (uint32_t)((NCHK - 1 - bl) / NSTAGE + 1);
        MBARRIER_WAIT_PARITY(smem_base + 16 + 8 * bl, (uses - 1u) & 1u);
    }
    TCGEN05_FENCE_AFTER();

    // epilogue: warp w -> rows (w&3)*32+lid, cols (w>>2)*64..+63
    {
        const int sub = wid & 3;
        const int colb = (wid >> 2) * 64;
        uint32_t d0[32], d1[32];
        TCGEN05_LD_32X32B_X32(d0, tmem_base + colb);
        TCGEN05_LD_32X32B_X32(d1, tmem_base + colb + 32);
        TCGEN05_WAIT_LD();
        float* crow = C + (size_t)(bm + sub * 32 + lid) * DM + bn + colb;
#pragma unroll
        for (int q = 0; q < 8; q++) {
            float4 v0 = make_float4(__uint_as_float(d0[q * 4 + 0]), __uint_as_float(d0[q * 4 + 1]),
                                    __uint_as_float(d0[q * 4 + 2]), __uint_as_float(d0[q * 4 + 3]));
            *reinterpret_cast<float4*>(crow + q * 4) = v0;
            float4 v1 = make_float4(__uint_as_float(d1[q * 4 + 0]), __uint_as_float(d1[q * 4 + 1]),
                                    __uint_as_float(d1[q * 4 + 2]), __uint_as_float(d1[q * 4 + 3]));
            *reinterpret_cast<float4*>(crow + 32 + q * 4) = v1;
        }
    }
    __syncthreads();
    if (wid == 0) {
        TCGEN05_RELINQUISH();
        TCGEN05_DEALLOC(tmem_base, 128);
    }

#else // ---------------- WMMA fallback (base sm_103 pass) ----------------
    // smem tiles, stride 72 elements (144B), 4 matrices of 128x64 bf16
    __nv_bfloat16* As_h = reinterpret_cast<__nv_bfloat16*>(smem);
    __nv_bfloat16* As_l = As_h + 128 * 72;
    __nv_bfloat16* Bs_h = As_l + 128 * 72;
    __nv_bfloat16* Bs_l = Bs_h + 128 * 72;

    const int wm = wid >> 2; // 0..1
    const int wn = wid & 3;  // 0..3

    wmma::fragment<wmma::accumulator, 16, 16, 16, float> acc[4][2];
#pragma unroll
    for (int i = 0; i < 4; i++)
#pragma unroll
        for (int j = 0; j < 2; j++)
            wmma::fill_fragment(acc[i][j], 0.0f);

#pragma unroll 1
    for (int c = 0; c < NCHK; c++) {
        const int kc = c * KCH;
#pragma unroll
        for (int p = 0; p < 16; p++) {
            const int mat = p >> 2;
            const int row = (p & 3) * 32 + r0;
            const __nv_bfloat16* src =
                (mat == 0) ? pAh : (mat == 1) ? pAl : (mat == 2) ? pBh : pBl;
            __nv_bfloat16* dst =
                (mat == 0) ? As_h : (mat == 1) ? As_l : (mat == 2) ? Bs_h : Bs_l;
            uint4 val = *reinterpret_cast<const uint4*>(
                src + (size_t)row * DM + kc + t16 * 8);
            *reinterpret_cast<uint4*>(dst + row * 72 + t16 * 8) = val;
        }
        __syncthreads();

#pragma unroll
        for (int ks = 0; ks < 4; ks++) {
            wmma::fragment<wmma::matrix_a, 16, 16, 16, __nv_bfloat16, wmma::row_major> ah[4], al[4];
            wmma::fragment<wmma::matrix_b, 16, 16, 16, __nv_bfloat16, wmma::col_major> bh[2], bl[2];
#pragma unroll
            for (int i = 0; i < 4; i++) {
                const int off = (wm * 64 + i * 16) * 72 + ks * 16;
                wmma::load_matrix_sync(ah[i], As_h + off, 72);
                wmma::load_matrix_sync(al[i], As_l + off, 72);
            }
#pragma unroll
            for (int j = 0; j < 2; j++) {
                const int off = (wn * 32 + j * 16) * 72 + ks * 16;
                wmma::load_matrix_sync(bh[j], Bs_h + off, 72);
                wmma::load_matrix_sync(bl[j], Bs_l + off, 72);
            }
#pragma unroll
            for (int i = 0; i < 4; i++)
#pragma unroll
                for (int j = 0; j < 2; j++) {
                    wmma::mma_sync(acc[i][j], al[i], bh[j], acc[i][j]);
                    wmma::mma_sync(acc[i][j], ah[i], bl[j], acc[i][j]);
                    wmma::mma_sync(acc[i][j], ah[i], bh[j], acc[i][j]);
                }
        }
        __syncthreads();
    }

#pragma unroll
    for (int i = 0; i < 4; i++)
#pragma unroll
        for (int j = 0; j < 2; j++)
            wmma::store_matrix_sync(
                C + (size_t)(bm + wm * 64 + i * 16) * DM + bn + wn * 32 + j * 16,
                acc[i][j], DM, wmma::mem_row_major);
#endif
}

// ===========================================================================
// Chunked local attention; writes bf16 hi/lo splits directly.
// ===========================================================================
#define ATTN_SMEM_FLOATS (64 * 65 + 128 * 65 + 128 * 65 + 64 * 130)
#define ATTN_SMEM_BYTES (ATTN_SMEM_FLOATS * 4)

__global__ __launch_bounds__(128) void attn_kernel(
    const float* __restrict__ q, const float* __restrict__ k,
    const float* __restrict__ v, __nv_bfloat16* __restrict__ oh,
    __nv_bfloat16* __restrict__ ol)
{
    extern __shared__ float smemf[];
    float* Qs = smemf;            // [64][65]
    float* Ks = Qs + 64 * 65;     // [128][65]
    float* Vs = Ks + 128 * 65;    // [128][65]
    float* Ss = Vs + 128 * 65;    // [64][130]

    const int bid = blockIdx.x;
    const int rtile = bid & 3;
    const int head = (bid >> 2) & 15;
    const int chunk = (bid >> 6) & (NCHUNK - 1);
    const int b = bid >> 11;

    const int tid = threadIdx.x;
    const int c0 = rtile * 64 - 64;
    const size_t base = ((size_t)(b * SEQ + chunk * 256)) * DM + head * HD;

    for (int idx = tid; idx < 64 * 16; idx += 128) {
        int row = idx >> 4;
        int c = (idx & 15) << 2;
        float4 val = *reinterpret_cast<const float4*>(
            q + base + (size_t)(rtile * 64 + row) * DM + c);
        float* dst = Qs + row * 65 + c;
        dst[0] = val.x; dst[1] = val.y; dst[2] = val.z; dst[3] = val.w;
    }
    for (int idx = tid; idx < 128 * 16; idx += 128) {
        int row = idx >> 4;
        int c = (idx & 15) << 2;
        int jc = c0 + row;
        float4 kv = make_float4(0.f, 0.f, 0.f, 0.f);
        float4 vv = make_float4(0.f, 0.f, 0.f, 0.f);
        if (jc >= 0) {
            kv = *reinterpret_cast<const float4*>(k + base + (size_t)jc * DM + c);
            vv = *reinterpret_cast<const float4*>(v + base + (size_t)jc * DM + c);
        }
        float* dk = Ks + row * 65 + c;
        dk[0] = kv.x; dk[1] = kv.y; dk[2] = kv.z; dk[3] = kv.w;
        float* dv = Vs + row * 65 + c;
        dv[0] = vv.x; dv[1] = vv.y; dv[2] = vv.z; dv[3] = vv.w;
    }
    __syncthreads();

    {
        const int rg = tid >> 3;
        const int cg = tid & 7;
        float acc[4][16];
#pragma unroll
        for (int r = 0; r < 4; r++)
#pragma unroll
            for (int jj = 0; jj < 16; jj++) acc[r][jj] = 0.f;

        for (int d = 0; d < 64; d++) {
            float qv0 = Qs[rg * 65 + d];
            float qv1 = Qs[(rg + 16) * 65 + d];
            float qv2 = Qs[(rg + 32) * 65 + d];
            float qv3 = Qs[(rg + 48) * 65 + d];
#pragma unroll
            for (int jj = 0; jj < 16; jj++) {
                float kv = Ks[(cg + 8 * jj) * 65 + d];
                acc[0][jj] += qv0 * kv;
                acc[1][jj] += qv1 * kv;
                acc[2][jj] += qv2 * kv;
                acc[3][jj] += qv3 * kv;
            }
        }
        const float scale = 0.125f;
#pragma unroll
        for (int r = 0; r < 4; r++)
#pragma unroll
            for (int jj = 0; jj < 16; jj++)
                Ss[(rg + 16 * r) * 130 + cg + 8 * jj] = acc[r][jj] * scale;
    }
    __syncthreads();

    {
        const int i = tid >> 1;
        const int half = tid & 1;
        const int lo = (rtile == 0) ? 64 : i;
        const int hi = i + 64;
        float* row = Ss + i * 130 + half * 64;
        const int jbase = half * 64;

        float m = -1e30f;
#pragma unroll
        for (int jj = 0; jj < 64; jj++) {
            int j = jbase + jj;
            if (j >= lo && j <= hi) m = fmaxf(m, row[jj]);
        }
        m = fmaxf(m, __shfl_xor_sync(0xffffffffu, m, 1));

        float s = 0.f;
#pragma unroll
        for (int jj = 0; jj < 64; jj++) {
            int j = jbase + jj;
            float e = 0.f;
            if (j >= lo && j <= hi) {
                e = __expf(row[jj] - m);
                s += e;
            }
            row[jj] = e;
        }
        s += __shfl_xor_sync(0xffffffffu, s, 1);
        float inv = 1.0f / s;
#pragma unroll
        for (int jj = 0; jj < 64; jj++) row[jj] *= inv;
    }
    __syncthreads();

    {
        const int rg = tid >> 2;
        const int cg = tid & 3;
        float acc0[16], acc1[16];
#pragma unroll
        for (int dd = 0; dd < 16; dd++) { acc0[dd] = 0.f; acc1[dd] = 0.f; }

        for (int j = 0; j < 128; j++) {
            float p0 = Ss[rg * 130 + j];
            float p1 = Ss[(rg + 32) * 130 + j];
#pragma unroll
            for (int dd = 0; dd < 16; dd++) {
                float vv = Vs[j * 65 + cg * 16 + dd];
                acc0[dd] += p0 * vv;
                acc1[dd] += p1 * vv;
            }
        }
#pragma unroll
        for (int r = 0; r < 2; r++) {
            const float* accp = r ? acc1 : acc0;
            size_t off = base + (size_t)(rtile * 64 + rg + 32 * r) * DM + cg * 16;
#pragma unroll
            for (int d2 = 0; d2 < 8; d2++) {
                __nv_bfloat16 h0, h1, l0, l1;
                split1(accp[d2 * 2 + 0], h0, l0);
                split1(accp[d2 * 2 + 1], h1, l1);
                __nv_bfloat162 hp; hp.x = h0; hp.y = h1;
                __nv_bfloat162 lp; lp.x = l0; lp.y = l1;
                *reinterpret_cast<__nv_bfloat162*>(oh + off + d2 * 2) = hp;
                *reinterpret_cast<__nv_bfloat162*>(ol + off + d2 * 2) = lp;
            }
        }
    }
}

// ===========================================================================
// kernel_launch
// ===========================================================================
extern "C" void kernel_launch(void* const* d_in, const int* in_sizes, int n_in,
                              void* d_out, int out_size)
{
    (void)in_sizes; (void)n_in; (void)out_size;
    const float* x  = (const float*)d_in[0];
    const float* Wq = (const float*)d_in[1];
    const float* Wk = (const float*)d_in[2];
    const float* Wv = (const float*)d_in[3];
    const float* Wo = (const float*)d_in[4];
    float* out = (float*)d_out;

    float *q, *k, *v;
    __nv_bfloat16 *ah, *al, *wh, *wl;
    cudaGetSymbolAddress((void**)&q, g_q);
    cudaGetSymbolAddress((void**)&k, g_k);
    cudaGetSymbolAddress((void**)&v, g_v);
    cudaGetSymbolAddress((void**)&ah, g_ah);
    cudaGetSymbolAddress((void**)&al, g_al);
    cudaGetSymbolAddress((void**)&wh, g_wh);
    cudaGetSymbolAddress((void**)&wl, g_wl);

    cudaFuncSetAttribute(gemm_tc, cudaFuncAttributeMaxDynamicSharedMemorySize,
                         GEMM_SMEM);
    cudaFuncSetAttribute(attn_kernel, cudaFuncAttributeMaxDynamicSharedMemorySize,
                         ATTN_SMEM_BYTES);

    // 1) split x into bf16 hi/lo
    splitx_kernel<<<(MTOT * DM / 4) / 256, 256>>>(
        (const float4*)x, (__nv_bfloat162*)ah, (__nv_bfloat162*)al);

    // 2) transpose+split all four weights
    dim3 wgrid(DM / 32, DM / 32);
    dim3 wblk(32, 8);
    wtrans_kernel<<<wgrid, wblk>>>(Wq, wh + 0 * DM * DM, wl + 0 * DM * DM);
    wtrans_kernel<<<wgrid, wblk>>>(Wk, wh + 1 * DM * DM, wl + 1 * DM * DM);
    wtrans_kernel<<<wgrid, wblk>>>(Wv, wh + 2 * DM * DM, wl + 2 * DM * DM);
    wtrans_kernel<<<wgrid, wblk>>>(Wo, wh + 3 * DM * DM, wl + 3 * DM * DM);

    // 3) Q/K/V projections
    dim3 ggrid(DM / 128, MTOT / 128); // (8, 256)
    gemm_tc<<<ggrid, 256, GEMM_SMEM>>>(ah, al, wh + 0 * DM * DM, wl + 0 * DM * DM, q);
    gemm_tc<<<ggrid, 256, GEMM_SMEM>>>(ah, al, wh + 1 * DM * DM, wl + 1 * DM * DM, k);
    gemm_tc<<<ggrid, 256, GEMM_SMEM>>>(ah, al, wh + 2 * DM * DM, wl + 2 * DM * DM, v);

    // 4) attention (writes bf16 hi/lo into ah/al)
    attn_kernel<<<BATCH * NCHUNK * NH * 4, 128, ATTN_SMEM_BYTES>>>(q, k, v, ah, al);

    // 5) output projection
    gemm_tc<<<ggrid, 256, GEMM_SMEM>>>(ah, al, wh + 3 * DM * DM, wl + 3 * DM * DM, out);
}

// round 4
// speedup vs baseline: 2.4681x; 1.0001x over previous
#include <cuda_runtime.h>
#include <cuda_bf16.h>
#include <mma.h>
#include <cstdint>

using namespace nvcuda;

// ---------------- problem constants ----------------
#define BATCH 4
#define SEQ 8192
#define DM 1024
#define NH 16
#define HD 64
#define NCHUNK 32
#define MTOT (BATCH * SEQ) // 32768

// Feature gate: tcgen05 only exists in the compute_103a / compute_100a passes.
#if defined(__CUDA_ARCH__) && (defined(__CUDA_ARCH_FEAT_SM103_ALL) || defined(__CUDA_ARCH_FEAT_SM100_ALL))
#define HAS_TCGEN05 1
#else
#define HAS_TCGEN05 0
#endif

// ---------------- scratch (device globals; no allocs) ----------------
__device__ float g_q[MTOT * DM];
__device__ float g_k[MTOT * DM];
__device__ float g_v[MTOT * DM];
__device__ __nv_bfloat16 g_ah[MTOT * DM]; // hi split of x, later of attn-out
__device__ __nv_bfloat16 g_al[MTOT * DM]; // lo split
__device__ __nv_bfloat16 g_wh[4 * DM * DM]; // transposed weights hi (q,k,v,o)
__device__ __nv_bfloat16 g_wl[4 * DM * DM]; // transposed weights lo

// ---------------- PTX helpers (legal on base sm_103) ----------------
__device__ __forceinline__ uint32_t elect_one_pred() {
    uint32_t pred;
    asm volatile(
        "{\n\t.reg .pred p;\n\t"
        "elect.sync _|p, 0xFFFFFFFF;\n\t"
        "selp.b32 %0, 1, 0, p;\n\t}"
        : "=r"(pred));
    return pred;
}

__device__ __forceinline__ uint32_t smem_to_u32(const void* smem_ptr) {
    uint32_t addr;
    asm("{ .reg .u64 tmp; cvta.to.shared.u64 tmp, %1; cvt.u32.u64 %0, tmp; }"
        : "=r"(addr) : "l"(smem_ptr));
    return addr;
}

#define MBARRIER_INIT(mbar, count) \
    asm volatile("mbarrier.init.shared.b64 [%0], %1;" \
                 :: "r"((uint32_t)(mbar)), "r"((uint32_t)(count)) : "memory")

#define MBARRIER_WAIT_PARITY(mbar_smem_addr, phase_parity) do { \
    uint32_t _mbar = (uint32_t)(mbar_smem_addr); \
    uint32_t _parity = (uint32_t)(phase_parity); \
    uint32_t _done; \
    asm volatile( \
        "{\n\t.reg .pred p;\n\t" \
        "mbarrier.try_wait.parity.acquire.cta.shared::cta.b64 p, [%1], %2;\n\t" \
        "selp.b32 %0, 1, 0, p;\n\t}" \
        : "=r"(_done) : "r"(_mbar), "r"(_parity) : "memory"); \
    if (!_done) { \
        asm volatile( \
            "{\n\t.reg .pred P1;\n\t" \
            "WAIT_LOOP_%=:\n\t" \
            "mbarrier.try_wait.parity.acquire.cta.shared::cta.b64 P1, [%0], %1, 0x989680;\n\t" \
            "@P1 bra.uni WAIT_DONE_%=;\n\t" \
            "bra.uni WAIT_LOOP_%=;\n\t" \
            "WAIT_DONE_%=:\n\t}" \
            :: "r"(_mbar), "r"(_parity) : "memory"); \
    } \
} while (0)

#define FENCE_PROXY_ASYNC_SHARED_CTA() \
    asm volatile("fence.proxy.async.shared::cta;" ::: "memory")

#if HAS_TCGEN05
// ---------------- tcgen05 helpers (compute_103a pass only) ----------------
#define TCGEN05_ALLOC(smem_result_addr, nCols) \
    asm volatile("tcgen05.alloc.cta_group::1.sync.aligned.shared::cta.b32 [%0], %1;" \
                 :: "r"((uint32_t)(smem_result_addr)), "r"((uint32_t)(nCols)) : "memory")

#define TCGEN05_DEALLOC(tmem_addr, nCols) \
    asm volatile("tcgen05.dealloc.cta_group::1.sync.aligned.b32 %0, %1;" \
                 :: "r"(tmem_addr), "r"((uint32_t)(nCols)))

#define TCGEN05_RELINQUISH() \
    asm volatile("tcgen05.relinquish_alloc_permit.cta_group::1.sync.aligned;")

#define TCGEN05_COMMIT(mbar) \
    asm volatile("tcgen05.commit.cta_group::1.mbarrier::arrive::one.shared::cluster.b64 [%0];" \
                 :: "r"((uint32_t)(mbar)) : "memory")

#define TCGEN05_FENCE_AFTER() \
    asm volatile("tcgen05.fence::after_thread_sync;" ::: "memory")

#define TCGEN05_WAIT_LD() \
    asm volatile("tcgen05.wait::ld.sync.aligned;" ::: "memory")

#define TCGEN05_LD_32X32B_X32(r, tmem_addr) \
    asm volatile( \
        "tcgen05.ld.sync.aligned.32x32b.x32.b32 " \
        "{%0, %1, %2, %3, %4, %5, %6, %7, " \
        " %8, %9, %10, %11, %12, %13, %14, %15, " \
        " %16, %17, %18, %19, %20, %21, %22, %23, " \
        " %24, %25, %26, %27, %28, %29, %30, %31}, [%32];" \
        : "=r"((r)[0]),  "=r"((r)[1]),  "=r"((r)[2]),  "=r"((r)[3]), \
          "=r"((r)[4]),  "=r"((r)[5]),  "=r"((r)[6]),  "=r"((r)[7]), \
          "=r"((r)[8]),  "=r"((r)[9]),  "=r"((r)[10]), "=r"((r)[11]), \
          "=r"((r)[12]), "=r"((r)[13]), "=r"((r)[14]), "=r"((r)[15]), \
          "=r"((r)[16]), "=r"((r)[17]), "=r"((r)[18]), "=r"((r)[19]), \
          "=r"((r)[20]), "=r"((r)[21]), "=r"((r)[22]), "=r"((r)[23]), \
          "=r"((r)[24]), "=r"((r)[25]), "=r"((r)[26]), "=r"((r)[27]), \
          "=r"((r)[28]), "=r"((r)[29]), "=r"((r)[30]), "=r"((r)[31]) \
        : "r"(tmem_addr))

// SW128 K-major descriptor: LBO=1, SBO=64, version=1
static constexpr uint64_t SMEM_DESC_BASE_SW128 =
    (uint64_t(2) << 61) | (uint64_t(1) << 46) | (uint64_t(64) << 32) | (uint64_t(1) << 16);
#define MAKE_SMEM_DESC(base_addr) \
    (SMEM_DESC_BASE_SW128 | ((uint64_t)((base_addr) >> 4) & 0x3FFF))

__device__ __forceinline__ void tcgen05_mma_f16_ss_cg1(
    uint32_t d_tmem, uint64_t a_desc, uint64_t b_desc, uint32_t idesc, uint32_t en)
{
    asm volatile(
        "{\n\t.reg .pred p;\n\t"
        "setp.ne.u32 p, %5, 0;\n\t"
        "tcgen05.mma.cta_group::1.kind::f16 [%0], %1, %2, %3, {%4, %4, %4, %4}, p;\n\t}"
        :: "r"(d_tmem), "l"(a_desc), "l"(b_desc), "r"(idesc), "r"(0u), "r"(en)
        : "memory");
}

// idesc: dtype F32, atype/btype BF16, N=128, M=128
#define GEMM_IDESC ((1u << 4) | (1u << 7) | (1u << 10) | (16u << 17) | (8u << 24))
#endif // HAS_TCGEN05

__device__ __forceinline__ void split1(float x, __nv_bfloat16& h, __nv_bfloat16& l) {
    h = __float2bfloat16_rn(x);
    l = __float2bfloat16_rn(x - __bfloat162float(h));
}

// ===========================================================================
// prep: split fp32 -> bf16 hi/lo
// ===========================================================================
__global__ __launch_bounds__(256) void splitx_kernel(
    const float4* __restrict__ in, __nv_bfloat162* __restrict__ h,
    __nv_bfloat162* __restrict__ l)
{
    size_t i = (size_t)blockIdx.x * 256 + threadIdx.x;
    float4 v = in[i];
    __nv_bfloat16 h0, h1, h2, h3, l0, l1, l2, l3;
    split1(v.x, h0, l0); split1(v.y, h1, l1);
    split1(v.z, h2, l2); split1(v.w, h3, l3);
    __nv_bfloat162 a; a.x = h0; a.y = h1;
    __nv_bfloat162 b; b.x = h2; b.y = h3;
    __nv_bfloat162 c; c.x = l0; c.y = l1;
    __nv_bfloat162 d; d.x = l2; d.y = l3;
    h[2 * i] = a; h[2 * i + 1] = b;
    l[2 * i] = c; l[2 * i + 1] = d;
}

// ===========================================================================
// prep: W[K,N] fp32 -> Wt[N,K] bf16 hi/lo (transpose + split)
// ===========================================================================
__global__ __launch_bounds__(256) void wtrans_kernel(
    const float* __restrict__ W, __nv_bfloat16* __restrict__ th,
    __nv_bfloat16* __restrict__ tl)
{
    __shared__ float tile[32][33];
    const int n0 = blockIdx.x * 32, k0 = blockIdx.y * 32;
    const int tx = threadIdx.x, ty = threadIdx.y;
    for (int r = ty; r < 32; r += 8)
        tile[r][tx] = W[(size_t)(k0 + r) * DM + n0 + tx];
    __syncthreads();
    for (int r = ty; r < 32; r += 8) {
        float v = tile[tx][r];
        __nv_bfloat16 h, l;
        split1(v, h, l);
        size_t o = (size_t)(n0 + r) * DM + k0 + tx;
        th[o] = h;
        tl[o] = l;
    }
}

// ===========================================================================
// GEMM: C[M,1024] = A[M,1024] @ Bt[1024,1024]^T, bf16x3 (hi/lo pre-split),
// fp32 accumulation. Tile 128x128, 256 threads.
//   - compute_103a pass: tcgen05 SS MMA, TMEM accumulator, 3-stage pipeline.
//   - base sm_103 pass:  WMMA (HMMA) fallback, BK=64 single buffer.
// ===========================================================================
#define KCH 64
#define NCHK (DM / KCH) // 16
#define NSTAGE 3
#define TILE_B (128 * 128)       // 16KB per bf16 tile (128 rows x 128B)
#define STAGE_B (4 * TILE_B)     // Ah, Al, Bh, Bl
#define GEMM_SMEM (1024 + NSTAGE * STAGE_B) // 197632 bytes

__global__ __launch_bounds__(256, 1) void gemm_tc(
    const __nv_bfloat16* __restrict__ Ahg, const __nv_bfloat16* __restrict__ Alg,
    const __nv_bfloat16* __restrict__ Bhg, const __nv_bfloat16* __restrict__ Blg,
    float* __restrict__ C)
{
    extern __shared__ char smem[];
    const int tid = threadIdx.x;
    const int wid = tid >> 5, lid = tid & 31;
    const int bm = blockIdx.y * 128, bn = blockIdx.x * 128;

    const __nv_bfloat16* pAh = Ahg + (size_t)bm * DM;
    const __nv_bfloat16* pAl = Alg + (size_t)bm * DM;
    const __nv_bfloat16* pBh = Bhg + (size_t)bn * DM;
    const __nv_bfloat16* pBl = Blg + (size_t)bn * DM;

    const int t16 = tid & 7;   // 16B unit within a 128B (64-elt) row
    const int r0 = tid >> 3;   // 0..31

#if HAS_TCGEN05
    const uint32_t smem_base = smem_to_u32(smem);
    if (tid == 0) {
#pragma unroll
        for (int s = 0; s < NSTAGE; s++) MBARRIER_INIT(smem_base + 16 + 8 * s, 1);
    }
    if (wid == 0) {
        TCGEN05_ALLOC(smem_base, 128);
    }
    __syncthreads();
    uint32_t tmem_base;
    asm volatile("ld.shared.b32 %0, [%1];" : "=r"(tmem_base) : "r"(smem_base));

#pragma unroll 1
    for (int c = 0; c < NCHK; c++) {
        const int b = c % NSTAGE;
        if (c >= NSTAGE) {
            const uint32_t par = ((uint32_t)(c / NSTAGE) - 1u) & 1u;
            MBARRIER_WAIT_PARITY(smem_base + 16 + 8 * b, par);
        }
        char* st = smem + 1024 + b * STAGE_B;
        const int kc = c * KCH;
#pragma unroll
        for (int p = 0; p < 16; p++) {
            const int mat = p >> 2;            // 0..3
            const int row = (p & 3) * 32 + r0; // 0..127
            const __nv_bfloat16* src =
                (mat == 0) ? pAh : (mat == 1) ? pAl : (mat == 2) ? pBh : pBl;
            uint4 val = *reinterpret_cast<const uint4*>(
                src + (size_t)row * DM + kc + t16 * 8);
            uint32_t off = (uint32_t)(row * 128 + t16 * 16);
            off ^= ((off >> 3) & 0x70);
            *reinterpret_cast<uint4*>(st + mat * TILE_B + off) = val;
        }
        FENCE_PROXY_ASYNC_SHARED_CTA();
        __syncthreads();
        if (wid == 0) {
            const uint32_t sb = smem_base + 1024 + b * STAGE_B;
            const uint64_t dAh = MAKE_SMEM_DESC(sb);
            const uint64_t dAl = MAKE_SMEM_DESC(sb + TILE_B);
            const uint64_t dBh = MAKE_SMEM_DESC(sb + 2 * TILE_B);
            const uint64_t dBl = MAKE_SMEM_DESC(sb + 3 * TILE_B);
            if (elect_one_pred()) {
#pragma unroll
                for (int j = 0; j < 4; j++) {
                    const uint32_t en0 = (c == 0 && j == 0) ? 0u : 1u;
                    tcgen05_mma_f16_ss_cg1(tmem_base, dAl + j * 2, dBh + j * 2, GEMM_IDESC, en0);
                    tcgen05_mma_f16_ss_cg1(tmem_base, dAh + j * 2, dBl + j * 2, GEMM_IDESC, 1u);
                    tcgen05_mma_f16_ss_cg1(tmem_base, dAh + j * 2, dBh + j * 2, GEMM_IDESC, 1u);
                }
                TCGEN05_COMMIT(smem_base + 16 + 8 * b);
            }
        }
    }

    {
        const int bl = (NCHK - 1) % NSTAGE;
        const uint32_t uses = (uint32_t)((NCHK - 1 - bl) / NSTAGE + 1);
        MBARRIER_WAIT_PARITY(smem_base + 16 + 8 * bl, (uses - 1u) & 1u);
    }
    TCGEN05_FENCE_AFTER();

    // epilogue: warp w -> rows (w&3)*32+lid, cols (w>>2)*64..+63
    {
        const int sub = wid & 3;
        const int colb = (wid >> 2) * 64;
        uint32_t d0[32], d1[32];
        TCGEN05_LD_32X32B_X32(d0, tmem_base + colb);
        TCGEN05_LD_32X32B_X32(d1, tmem_base + colb + 32);
        TCGEN05_WAIT_LD();
        float* crow = C + (size_t)(bm + sub * 32 + lid) * DM + bn + colb;
#pragma unroll
        for (int q = 0; q < 8; q++) {
            float4 v0 = make_float4(__uint_as_float(d0[q * 4 + 0]), __uint_as_float(d0[q * 4 + 1]),
                                    __uint_as_float(d0[q * 4 + 2]), __uint_as_float(d0[q * 4 + 3]));
            *reinterpret_cast<float4*>(crow + q * 4) = v0;
            float4 v1 = make_float4(__uint_as_float(d1[q * 4 + 0]), __uint_as_float(d1[q * 4 + 1]),
                                    __uint_as_float(d1[q * 4 + 2]), __uint_as_float(d1[q * 4 + 3]));
            *reinterpret_cast<float4*>(crow + 32 + q * 4) = v1;
        }
    }
    __syncthreads();
    if (wid == 0) {
        TCGEN05_RELINQUISH();
        TCGEN05_DEALLOC(tmem_base, 128);
    }

#else // ---------------- WMMA fallback (base sm_103 pass) ----------------
    // smem tiles, stride 72 elements (144B), 4 matrices of 128x64 bf16
    __nv_bfloat16* As_h = reinterpret_cast<__nv_bfloat16*>(smem);
    __nv_bfloat16* As_l = As_h + 128 * 72;
    __nv_bfloat16* Bs_h = As_l + 128 * 72;
    __nv_bfloat16* Bs_l = Bs_h + 128 * 72;

    const int wm = wid >> 2; // 0..1
    const int wn = wid & 3;  // 0..3

    wmma::fragment<wmma::accumulator, 16, 16, 16, float> acc[4][2];
#pragma unroll
    for (int i = 0; i < 4; i++)
#pragma unroll
        for (int j = 0; j < 2; j++)
            wmma::fill_fragment(acc[i][j], 0.0f);

#pragma unroll 1
    for (int c = 0; c < NCHK; c++) {
        const int kc = c * KCH;
#pragma unroll
        for (int p = 0; p < 16; p++) {
            const int mat = p >> 2;
            const int row = (p & 3) * 32 + r0;
            const __nv_bfloat16* src =
                (mat == 0) ? pAh : (mat == 1) ? pAl : (mat == 2) ? pBh : pBl;
            __nv_bfloat16* dst =
                (mat == 0) ? As_h : (mat == 1) ? As_l : (mat == 2) ? Bs_h : Bs_l;
            uint4 val = *reinterpret_cast<const uint4*>(
                src + (size_t)row * DM + kc + t16 * 8);
            *reinterpret_cast<uint4*>(dst + row * 72 + t16 * 8) = val;
        }
        __syncthreads();

#pragma unroll
        for (int ks = 0; ks < 4; ks++) {
            wmma::fragment<wmma::matrix_a, 16, 16, 16, __nv_bfloat16, wmma::row_major> ah[4], al[4];
            wmma::fragment<wmma::matrix_b, 16, 16, 16, __nv_bfloat16, wmma::col_major> bh[2], bl[2];
#pragma unroll
            for (int i = 0; i < 4; i++) {
                const int off = (wm * 64 + i * 16) * 72 + ks * 16;
                wmma::load_matrix_sync(ah[i], As_h + off, 72);
                wmma::load_matrix_sync(al[i], As_l + off, 72);
            }
#pragma unroll
            for (int j = 0; j < 2; j++) {
                const int off = (wn * 32 + j * 16) * 72 + ks * 16;
                wmma::load_matrix_sync(bh[j], Bs_h + off, 72);
                wmma::load_matrix_sync(bl[j], Bs_l + off, 72);
            }
#pragma unroll
            for (int i = 0; i < 4; i++)
#pragma unroll
                for (int j = 0; j < 2; j++) {
                    wmma::mma_sync(acc[i][j], al[i], bh[j], acc[i][j]);
                    wmma::mma_sync(acc[i][j], ah[i], bl[j], acc[i][j]);
                    wmma::mma_sync(acc[i][j], ah[i], bh[j], acc[i][j]);
                }
        }
        __syncthreads();
    }

#pragma unroll
    for (int i = 0; i < 4; i++)
#pragma unroll
        for (int j = 0; j < 2; j++)
            wmma::store_matrix_sync(
                C + (size_t)(bm + wm * 64 + i * 16) * DM + bn + wn * 32 + j * 16,
                acc[i][j], DM, wmma::mem_row_major);
#endif
}

// ===========================================================================
// Chunked local attention; writes bf16 hi/lo splits directly.
// ===========================================================================
#define ATTN_SMEM_FLOATS (64 * 65 + 128 * 65 + 128 * 65 + 64 * 130)
#define ATTN_SMEM_BYTES (ATTN_SMEM_FLOATS * 4)

__global__ __launch_bounds__(128) void attn_kernel(
    const float* __restrict__ q, const float* __restrict__ k,
    const float* __restrict__ v, __nv_bfloat16* __restrict__ oh,
    __nv_bfloat16* __restrict__ ol)
{
    extern __shared__ float smemf[];
    float* Qs = smemf;            // [64][65]
    float* Ks = Qs + 64 * 65;     // [128][65]
    float* Vs = Ks + 128 * 65;    // [128][65]
    float* Ss = Vs + 128 * 65;    // [64][130]

    const int bid = blockIdx.x;
    const int rtile = bid & 3;
    const int head = (bid >> 2) & 15;
    const int chunk = (bid >> 6) & (NCHUNK - 1);
    const int b = bid >> 11;

    const int tid = threadIdx.x;
    const int c0 = rtile * 64 - 64;
    const size_t base = ((size_t)(b * SEQ + chunk * 256)) * DM + head * HD;

    for (int idx = tid; idx < 64 * 16; idx += 128) {
        int row = idx >> 4;
        int c = (idx & 15) << 2;
        float4 val = *reinterpret_cast<const float4*>(
            q + base + (size_t)(rtile * 64 + row) * DM + c);
        float* dst = Qs + row * 65 + c;
        dst[0] = val.x; dst[1] = val.y; dst[2] = val.z; dst[3] = val.w;
    }
    for (int idx = tid; idx < 128 * 16; idx += 128) {
        int row = idx >> 4;
        int c = (idx & 15) << 2;
        int jc = c0 + row;
        float4 kv = make_float4(0.f, 0.f, 0.f, 0.f);
        float4 vv = make_float4(0.f, 0.f, 0.f, 0.f);
        if (jc >= 0) {
            kv = *reinterpret_cast<const float4*>(k + base + (size_t)jc * DM + c);
            vv = *reinterpret_cast<const float4*>(v + base + (size_t)jc * DM + c);
        }
        float* dk = Ks + row * 65 + c;
        dk[0] = kv.x; dk[1] = kv.y; dk[2] = kv.z; dk[3] = kv.w;
        float* dv = Vs + row * 65 + c;
        dv[0] = vv.x; dv[1] = vv.y; dv[2] = vv.z; dv[3] = vv.w;
    }
    __syncthreads();

    {
        const int rg = tid >> 3;
        const int cg = tid & 7;
        float acc[4][16];
#pragma unroll
        for (int r = 0; r < 4; r++)
#pragma unroll
            for (int jj = 0; jj < 16; jj++) acc[r][jj] = 0.f;

        for (int d = 0; d < 64; d++) {
            float qv0 = Qs[rg * 65 + d];
            float qv1 = Qs[(rg + 16) * 65 + d];
            float qv2 = Qs[(rg + 32) * 65 + d];
            float qv3 = Qs[(rg + 48) * 65 + d];
#pragma unroll
            for (int jj = 0; jj < 16; jj++) {
                float kv = Ks[(cg + 8 * jj) * 65 + d];
                acc[0][jj] += qv0 * kv;
                acc[1][jj] += qv1 * kv;
                acc[2][jj] += qv2 * kv;
                acc[3][jj] += qv3 * kv;
            }
        }
        const float scale = 0.125f;
#pragma unroll
        for (int r = 0; r < 4; r++)
#pragma unroll
            for (int jj = 0; jj < 16; jj++)
                Ss[(rg + 16 * r) * 130 + cg + 8 * jj] = acc[r][jj] * scale;
    }
    __syncthreads();

    {
        const int i = tid >> 1;
        const int half = tid & 1;
        const int lo = (rtile == 0) ? 64 : i;
        const int hi = i + 64;
        float* row = Ss + i * 130 + half * 64;
        const int jbase = half * 64;

        float m = -1e30f;
#pragma unroll
        for (int jj = 0; jj < 64; jj++) {
            int j = jbase + jj;
            if (j >= lo && j <= hi) m = fmaxf(m, row[jj]);
        }
        m = fmaxf(m, __shfl_xor_sync(0xffffffffu, m, 1));

        float s = 0.f;
#pragma unroll
        for (int jj = 0; jj < 64; jj++) {
            int j = jbase + jj;
            float e = 0.f;
            if (j >= lo && j <= hi) {
                e = __expf(row[jj] - m);
                s += e;
            }
            row[jj] = e;
        }
        s += __shfl_xor_sync(0xffffffffu, s, 1);
        float inv = 1.0f / s;
#pragma unroll
        for (int jj = 0; jj < 64; jj++) row[jj] *= inv;
    }
    __syncthreads();

    {
        const int rg = tid >> 2;
        const int cg = tid & 3;
        float acc0[16], acc1[16];
#pragma unroll
        for (int dd = 0; dd < 16; dd++) { acc0[dd] = 0.f; acc1[dd] = 0.f; }

        for (int j = 0; j < 128; j++) {
            float p0 = Ss[rg * 130 + j];
            float p1 = Ss[(rg + 32) * 130 + j];
#pragma unroll
            for (int dd = 0; dd < 16; dd++) {
                float vv = Vs[j * 65 + cg * 16 + dd];
                acc0[dd] += p0 * vv;
                acc1[dd] += p1 * vv;
            }
        }
#pragma unroll
        for (int r = 0; r < 2; r++) {
            const float* accp = r ? acc1 : acc0;
            size_t off = base + (size_t)(rtile * 64 + rg + 32 * r) * DM + cg * 16;
#pragma unroll
            for (int d2 = 0; d2 < 8; d2++) {
                __nv_bfloat16 h0, h1, l0, l1;
                split1(accp[d2 * 2 + 0], h0, l0);
                split1(accp[d2 * 2 + 1], h1, l1);
                __nv_bfloat162 hp; hp.x = h0; hp.y = h1;
                __nv_bfloat162 lp; lp.x = l0; lp.y = l1;
                *reinterpret_cast<__nv_bfloat162*>(oh + off + d2 * 2) = hp;
                *reinterpret_cast<__nv_bfloat162*>(ol + off + d2 * 2) = lp;
            }
        }
    }
}

// ===========================================================================
// kernel_launch
// ===========================================================================
extern "C" void kernel_launch(void* const* d_in, const int* in_sizes, int n_in,
                              void* d_out, int out_size)
{
    (void)in_sizes; (void)n_in; (void)out_size;
    const float* x  = (const float*)d_in[0];
    const float* Wq = (const float*)d_in[1];
    const float* Wk = (const float*)d_in[2];
    const float* Wv = (const float*)d_in[3];
    const float* Wo = (const float*)d_in[4];
    float* out = (float*)d_out;

    float *q, *k, *v;
    __nv_bfloat16 *ah, *al, *wh, *wl;
    cudaGetSymbolAddress((void**)&q, g_q);
    cudaGetSymbolAddress((void**)&k, g_k);
    cudaGetSymbolAddress((void**)&v, g_v);
    cudaGetSymbolAddress((void**)&ah, g_ah);
    cudaGetSymbolAddress((void**)&al, g_al);
    cudaGetSymbolAddress((void**)&wh, g_wh);
    cudaGetSymbolAddress((void**)&wl, g_wl);

    cudaFuncSetAttribute(gemm_tc, cudaFuncAttributeMaxDynamicSharedMemorySize,
                         GEMM_SMEM);
    cudaFuncSetAttribute(attn_kernel, cudaFuncAttributeMaxDynamicSharedMemorySize,
                         ATTN_SMEM_BYTES);

    // 1) split x into bf16 hi/lo
    splitx_kernel<<<(MTOT * DM / 4) / 256, 256>>>(
        (const float4*)x, (__nv_bfloat162*)ah, (__nv_bfloat162*)al);

    // 2) transpose+split all four weights
    dim3 wgrid(DM / 32, DM / 32);
    dim3 wblk(32, 8);
    wtrans_kernel<<<wgrid, wblk>>>(Wq, wh + 0 * DM * DM, wl + 0 * DM * DM);
    wtrans_kernel<<<wgrid, wblk>>>(Wk, wh + 1 * DM * DM, wl + 1 * DM * DM);
    wtrans_kernel<<<wgrid, wblk>>>(Wv, wh + 2 * DM * DM, wl + 2 * DM * DM);
    wtrans_kernel<<<wgrid, wblk>>>(Wo, wh + 3 * DM * DM, wl + 3 * DM * DM);

    // 3) Q/K/V projections
    dim3 ggrid(DM / 128, MTOT / 128); // (8, 256)
    gemm_tc<<<ggrid, 256, GEMM_SMEM>>>(ah, al, wh + 0 * DM * DM, wl + 0 * DM * DM, q);
    gemm_tc<<<ggrid, 256, GEMM_SMEM>>>(ah, al, wh + 1 * DM * DM, wl + 1 * DM * DM, k);
    gemm_tc<<<ggrid, 256, GEMM_SMEM>>>(ah, al, wh + 2 * DM * DM, wl + 2 * DM * DM, v);

    // 4) attention (writes bf16 hi/lo into ah/al)
    attn_kernel<<<BATCH * NCHUNK * NH * 4, 128, ATTN_SMEM_BYTES>>>(q, k, v, ah, al);

    // 5) output projection
    gemm_tc<<<ggrid, 256, GEMM_SMEM>>>(ah, al, wh + 3 * DM * DM, wl + 3 * DM * DM, out);
}